// round 9
// baseline (speedup 1.0000x reference)
// R8: R7 design + guaranteed LDS.128 weight loads (ulonglong2) in both hot loops.
#include <cuda_runtime.h>

#define BSZ 2
#define Hh 96
#define Ww 96
#define HW (Hh*Ww)
#define G 8
#define K 9
#define CG 16          // channels per group
#define CIN_DCN 1152   // 128*9

typedef unsigned long long u64;

// ---------------- packed f32x2 helpers ----------------
__device__ __forceinline__ u64 pack2(float x) {
    u64 r; unsigned xi = __float_as_uint(x);
    asm("mov.b64 %0, {%1, %1};" : "=l"(r) : "r"(xi));
    return r;
}
__device__ __forceinline__ void fma2(u64& d, u64 a, u64 b, u64 c) {
    asm("fma.rn.f32x2 %0, %1, %2, %3;" : "=l"(d) : "l"(a), "l"(b), "l"(c));
}
__device__ __forceinline__ float2 unpack2(u64 v) {
    unsigned lo, hi;
    asm("mov.b64 {%0, %1}, %2;" : "=r"(lo), "=r"(hi) : "l"(v));
    return make_float2(__uint_as_float(lo), __uint_as_float(hi));
}

// ---------------- scratch (no allocations allowed) ----------------
__device__ float g_t1  [BSZ*128*HW];
__device__ float g_t2  [BSZ*128*HW];
__device__ float g_tom [BSZ*216*HW];
__device__ float g_tv  [BSZ*CIN_DCN*HW];   // sampled deform columns
__device__ float g_tfea[BSZ*128*HW];

// ---------------- direct 3x3 conv, packed f32x2 ----------------
// MODE 0: input = x
// MODE 1: input = x - x2           (CIN channels each)
// MODE 2: input = concat(x, x2)    (CIN=256, 128 each)
// Block: 256 threads. Tile: 32(w) x 16(h) pixels, 32 output channels.
// Thread: ocg = t>>7 selects oc half (16 oc = 8 pairs); 128 lanes cover
// 32 cols x 4 row-slots; each thread computes 4 pixels (rows r, r+4, r+8, r+12).
// OC is compile-time: for OC%32==0 all tail guards vanish (straight-line STG).
// launch_bounds(256, 2): pins regs <= 128 so the one-wave/occ-2 schedule holds.
template<int CIN, int OC, int MODE, bool RELU>
__global__ void __launch_bounds__(256, 2) conv3x3_k(
    const float* __restrict__ x, const float* __restrict__ x2,
    const float* __restrict__ wgt, const float* __restrict__ bias,
    float* __restrict__ out)
{
    const int ICC = 8;
    constexpr int OCTILES = (OC + 31) >> 5;
    constexpr bool FULL = (OC % 32 == 0);
    __shared__ float s_in[ICC][18][34];
    __shared__ __align__(16) float s_w[ICC*9*32];   // [c][k][o(32)], o contiguous

    const int t    = threadIdx.x;
    const int ocg  = t >> 7;        // 0 or 1
    const int lane = t & 127;
    const int col  = lane & 31;     // 0..31
    const int row4 = lane >> 5;     // 0..3
    const int w0 = blockIdx.x * 32;
    const int h0 = blockIdx.y * 16;
    const int b      = blockIdx.z / OCTILES;
    const int ocb32  = (blockIdx.z % OCTILES) << 5;
    const int ocbase = ocb32 + (ocg << 4);          // this thread's 16-oc base

    u64 acc[4][8];
#pragma unroll
    for (int p = 0; p < 4; p++)
#pragma unroll
        for (int j = 0; j < 8; j++) acc[p][j] = 0ull;

    for (int ic0 = 0; ic0 < CIN; ic0 += ICC) {
        // ---- input tile: ICC x 18 x 34, zero-padded halo ----
        for (int idx = t; idx < ICC*18*34; idx += 256) {
            int c   = idx / (18*34);
            int rem = idx - c*(18*34);
            int r   = rem / 34;
            int cc  = rem - r*34;
            int hh = h0 + r - 1;
            int ww = w0 + cc - 1;
            float v = 0.f;
            if (hh >= 0 && hh < Hh && ww >= 0 && ww < Ww) {
                int cidx = ic0 + c;
                if (MODE == 2) {
                    const float* src = (cidx < 128)
                        ? (x  + ((size_t)b*128 + cidx      )*HW)
                        : (x2 + ((size_t)b*128 + (cidx-128))*HW);
                    v = src[hh*Ww + ww];
                } else {
                    size_t off = ((size_t)b*CIN + cidx)*HW + (size_t)hh*Ww + ww;
                    v = x[off];
                    if (MODE == 1) v -= x2[off];
                }
            }
            s_in[c][r][cc] = v;
        }
        // ---- weights: [c][k][o], o contiguous -> LDS.128 quads ----
        for (int idx = t; idx < ICC*9*32; idx += 256) {
            int o  = idx / 72;
            int ck = idx - o*72;
            int c  = ck / 9;
            int k  = ck - c*9;
            int oc = ocb32 + o;
            float wv = 0.f;
            if (FULL || oc < OC) wv = wgt[((size_t)oc*CIN + ic0 + c)*9 + k];
            s_w[(c*9 + k)*32 + o] = wv;
        }
        __syncthreads();

        for (int c = 0; c < ICC; ++c) {     // rolled: keeps loop body in I$
#pragma unroll
            for (int k = 0; k < 9; k++) {
                // 64B weight block, 64B-aligned -> 4x LDS.128 guaranteed
                const ulonglong2* wp =
                    (const ulonglong2*)&s_w[(c*9 + k)*32 + (ocg << 4)];
                u64 wr[8];
#pragma unroll
                for (int q = 0; q < 4; q++) {
                    ulonglong2 w2v = wp[q];
                    wr[2*q]   = w2v.x;
                    wr[2*q+1] = w2v.y;
                }
#pragma unroll
                for (int p = 0; p < 4; p++) {
                    float xin = s_in[c][row4 + 4*p + k/3][col + k%3];
                    u64 xp = pack2(xin);
#pragma unroll
                    for (int j = 0; j < 8; j++) fma2(acc[p][j], wr[j], xp, acc[p][j]);
                }
            }
        }
        __syncthreads();
    }

    // ---- epilogue (guard-free when OC%32==0) ----
#pragma unroll
    for (int p = 0; p < 4; p++) {
        const int hh = h0 + row4 + 4*p;
        const int ww = w0 + col;
#pragma unroll
        for (int j = 0; j < 8; j++) {
            float2 v = unpack2(acc[p][j]);
            int oc0 = ocbase + 2*j;
            if (FULL || oc0 < OC) {
                float r0 = v.x + bias[oc0];
                if (RELU) r0 = fmaxf(r0, 0.f);
                out[((size_t)b*OC + oc0)*HW + (size_t)hh*Ww + ww] = r0;
            }
            if (FULL || oc0 + 1 < OC) {
                float r1 = v.y + bias[oc0 + 1];
                if (RELU) r1 = fmaxf(r1, 0.f);
                out[((size_t)b*OC + oc0 + 1)*HW + (size_t)hh*Ww + ww] = r1;
            }
        }
    }
}

// ---------------- deformable sampling: build column tensor ----------------
// One thread per (b, g, k, hw). Writes v[b, (g*16+c)*9 + k, hw] for c in [0,16).
__global__ void dcn_sample_k(const float* __restrict__ x, const float* __restrict__ om,
                             float* __restrict__ v)
{
    int t = blockIdx.x * blockDim.x + threadIdx.x;
    const int total = BSZ * G * K * HW;
    if (t >= total) return;
    int hw = t % HW;
    int k  = (t / HW) % K;
    int g  = (t / (HW * K)) % G;
    int b  =  t / (HW * K * G);
    int h = hw / Ww, w = hw % Ww;

    const float* omb = om + (size_t)b*216*HW;
    float dy = omb[(size_t)(g*18 + 2*k    )*HW + hw];
    float dx = omb[(size_t)(g*18 + 2*k + 1)*HW + hw];
    float mk = omb[(size_t)(144 + g*9 + k )*HW + hw];
    float m  = 1.f / (1.f + __expf(-mk));   // MUFU.EX2; |err|<=2ulp << 1e-3 gate

    int ky = k / 3, kx = k % 3;
    float py = dy + (float)(ky + h - 1);
    float px = dx + (float)(kx + w - 1);
    float y0f = floorf(py), x0f = floorf(px);
    float ly = py - y0f, lx = px - x0f;
    int y0 = (int)y0f, x0 = (int)x0f;
    int y1 = y0 + 1,   x1 = x0 + 1;
    bool vy0 = (y0 >= 0) & (y0 < Hh), vy1 = (y1 >= 0) & (y1 < Hh);
    bool vx0 = (x0 >= 0) & (x0 < Ww), vx1 = (x1 >= 0) & (x1 < Ww);
    int yc0 = min(max(y0, 0), Hh-1), yc1 = min(max(y1, 0), Hh-1);
    int xc0 = min(max(x0, 0), Ww-1), xc1 = min(max(x1, 0), Ww-1);

    float w00 = (vy0 & vx0) ? (1.f-ly)*(1.f-lx)*m : 0.f;
    float w01 = (vy0 & vx1) ? (1.f-ly)*lx      *m : 0.f;
    float w10 = (vy1 & vx0) ? ly*(1.f-lx)      *m : 0.f;
    float w11 = (vy1 & vx1) ? ly*lx            *m : 0.f;

    int i00 = yc0*Ww + xc0, i01 = yc0*Ww + xc1;
    int i10 = yc1*Ww + xc0, i11 = yc1*Ww + xc1;

    const float* xb = x + ((size_t)b*128 + g*CG)*HW;
    float* vb = v + (size_t)b*CIN_DCN*HW + (size_t)(g*CG)*9*HW + (size_t)k*HW + hw;

#pragma unroll
    for (int c = 0; c < CG; c++) {
        const float* xc = xb + (size_t)c*HW;
        float val = w00*xc[i00] + w01*xc[i01] + w10*xc[i10] + w11*xc[i11];
        vb[(size_t)c*9*HW] = val;
    }
}

// ---------------- 1x1 conv over 1152 sampled channels (DCN GEMM), f32x2 ----------------
// Block: 256 threads, each computes 4 pixels (stride 256) x 16 oc.
// Tile: 1024 pixels x 16 oc per block. Input fill via LDG.128.
__global__ void __launch_bounds__(256, 2) conv1x1_k(
    const float* __restrict__ x, const float* __restrict__ wgt,
    const float* __restrict__ bias, float* __restrict__ out)
{
    const int CIN = CIN_DCN, OC = 128, ICC = 8;
    __shared__ __align__(16) float s_in[ICC][1024];
    __shared__ __align__(16) float s_w[ICC*16];   // [c][o(16)]

    const int t   = threadIdx.x;
    const int hw0 = blockIdx.x * 1024;
    const int b   = blockIdx.y >> 3;
    const int ocb = (blockIdx.y & 7) << 4;

    u64 acc[4][8];
#pragma unroll
    for (int p = 0; p < 4; p++)
#pragma unroll
        for (int j = 0; j < 8; j++) acc[p][j] = 0ull;

    const float* xb = x + (size_t)b*CIN*HW + hw0;

    for (int ic0 = 0; ic0 < CIN; ic0 += ICC) {
        // vectorized tile fill: one LDG.128 per (thread, channel)
#pragma unroll
        for (int c = 0; c < ICC; c++) {
            const float4* src = (const float4*)(xb + (size_t)(ic0 + c)*HW);
            ((float4*)&s_in[c][0])[t] = src[t];
        }
        if (t < ICC*16) {   // c fast within gmem row -> coalesced
            int c = t & (ICC-1), o = t >> 3;
            s_w[c*16 + o] = wgt[(size_t)(ocb + o)*CIN + ic0 + c];
        }
        __syncthreads();

        for (int c = 0; c < ICC; ++c) {
            // 64B weight row, 64B-aligned -> 4x LDS.128 guaranteed
            const ulonglong2* wp = (const ulonglong2*)&s_w[c*16];
            u64 wr[8];
#pragma unroll
            for (int q = 0; q < 4; q++) {
                ulonglong2 w2v = wp[q];
                wr[2*q]   = w2v.x;
                wr[2*q+1] = w2v.y;
            }
#pragma unroll
            for (int p = 0; p < 4; p++) {
                u64 xp = pack2(s_in[c][t + 256*p]);
#pragma unroll
                for (int j = 0; j < 8; j++) fma2(acc[p][j], wr[j], xp, acc[p][j]);
            }
        }
        __syncthreads();
    }

#pragma unroll
    for (int p = 0; p < 4; p++) {
#pragma unroll
        for (int j = 0; j < 8; j++) {
            float2 v = unpack2(acc[p][j]);
            int oc0 = ocb + 2*j;
            float r0 = fmaxf(v.x + bias[oc0],     0.f);   // relu(fea)
            float r1 = fmaxf(v.y + bias[oc0 + 1], 0.f);
            out[((size_t)b*OC + oc0    )*HW + hw0 + t + 256*p] = r0;
            out[((size_t)b*OC + oc0 + 1)*HW + hw0 + t + 256*p] = r1;
        }
    }
}

// ---------------- launch ----------------
extern "C" void kernel_launch(void* const* d_in, const int* in_sizes, int n_in,
                              void* d_out, int out_size)
{
    const float* R1    = (const float*)d_in[0];
    const float* Q0    = (const float*)d_in[1];
    const float* w1    = (const float*)d_in[2];
    const float* b1    = (const float*)d_in[3];
    const float* w2    = (const float*)d_in[4];
    const float* b2    = (const float*)d_in[5];
    const float* w_om  = (const float*)d_in[6];
    const float* b_om  = (const float*)d_in[7];
    const float* w_dcn = (const float*)d_in[8];
    const float* b_dcn = (const float*)d_in[9];
    const float* w_rq  = (const float*)d_in[10];
    const float* b_rq  = (const float*)d_in[11];
    float* out = (float*)d_out;

    float *t1, *t2, *tom, *tv, *tfea;
    cudaGetSymbolAddress((void**)&t1,   g_t1);
    cudaGetSymbolAddress((void**)&t2,   g_t2);
    cudaGetSymbolAddress((void**)&tom,  g_tom);
    cudaGetSymbolAddress((void**)&tv,   g_tv);
    cudaGetSymbolAddress((void**)&tfea, g_tfea);

    dim3 blk(256);
    // grids: x = W/32 = 3, y = H/16 = 6, z = B * ceil(OC/32)

    // off = relu(conv3x3(R1-Q0, w1, b1))
    conv3x3_k<128,128,1,true ><<<dim3(3,6,BSZ*4), blk>>>(R1, Q0, w1, b1, t1);
    // off = relu(conv3x3(off, w2, b2))
    conv3x3_k<128,128,0,true ><<<dim3(3,6,BSZ*4), blk>>>(t1, nullptr, w2, b2, t2);
    // om = conv3x3(off, w_om, b_om)  (216 ch, no relu; tail tile keeps guards)
    conv3x3_k<128,216,0,false><<<dim3(3,6,BSZ*7), blk>>>(t2, nullptr, w_om, b_om, tom);
    // deformable sampling -> column tensor
    dcn_sample_k<<<(BSZ*G*K*HW + 255)/256, 256>>>(R1, tom, tv);
    // fea = relu(GEMM over 1152 sampled channels); HW/1024 = 9 exactly
    conv1x1_k<<<dim3(HW/1024, BSZ*8), blk>>>(tv, w_dcn, b_dcn, tfea);
    // out = relu(conv3x3(concat(fea, Q0), w_rq, b_rq))
    conv3x3_k<256,128,2,true ><<<dim3(3,6,BSZ*4), blk>>>(tfea, Q0, w_rq, b_rq, out);
}